// round 10
// baseline (speedup 1.0000x reference)
#include <cuda_runtime.h>
#include <cstdint>

#define B_DIM 64
#define S_DIM 512
#define W_DIM 256
#define D_DIM 768
#define N_DIM 96
#define MT 64
#define KT 64
#define NUM_KT 12
#define THREADS 256

#define RS 144                        // fp16 tile row stride (64*2 + 16 pad)
#define A32_STAGE 16384               // 64 rows * 256 B (linear, no pad)
#define A16_STAGE 9216                // 64 * 144
#define B_STAGE   13824               // 96 * 144
#define SM_A32 1024
#define SM_A16 (SM_A32 + 3 * A32_STAGE)     // 50176
#define SM_B   (SM_A16 + 2 * A16_STAGE)     // 68608
#define SMEM_TOTAL (SM_B + 3 * B_STAGE)     // 110080

// Pre-converted fp16 copy of clsw: [96][768] fp16 (row stride 1536 B)
__device__ __align__(16) unsigned char g_Bh[N_DIM * D_DIM * 2];

static __device__ __forceinline__ uint32_t smem_u32(const void* p) {
    uint32_t a;
    asm("{ .reg .u64 t; cvta.to.shared.u64 t, %1; cvt.u32.u64 %0, t; }" : "=r"(a) : "l"(p));
    return a;
}

static __device__ __forceinline__ void ldsm4(uint32_t* r, uint32_t addr) {
    asm volatile("ldmatrix.sync.aligned.m8n8.x4.shared.b16 {%0,%1,%2,%3}, [%4];"
                 : "=r"(r[0]), "=r"(r[1]), "=r"(r[2]), "=r"(r[3]) : "r"(addr));
}

static __device__ __forceinline__ void ldsm2(uint32_t* r, uint32_t addr) {
    asm volatile("ldmatrix.sync.aligned.m8n8.x2.shared.b16 {%0,%1}, [%2];"
                 : "=r"(r[0]), "=r"(r[1]) : "r"(addr));
}

static __device__ __forceinline__ void mma_f16(float* c, const uint32_t* a, const uint32_t* b) {
    asm volatile(
        "mma.sync.aligned.m16n8k16.row.col.f32.f16.f16.f32 "
        "{%0,%1,%2,%3}, {%4,%5,%6,%7}, {%8,%9}, {%0,%1,%2,%3};"
        : "+f"(c[0]), "+f"(c[1]), "+f"(c[2]), "+f"(c[3])
        : "r"(a[0]), "r"(a[1]), "r"(a[2]), "r"(a[3]), "r"(b[0]), "r"(b[1]));
}

static __device__ __forceinline__ uint2 cvt_f16x4(float4 v) {
    uint2 r;   // low half of each word = lower-k element
    asm("cvt.rn.f16x2.f32 %0, %1, %2;" : "=r"(r.x) : "f"(v.y), "f"(v.x));
    asm("cvt.rn.f16x2.f32 %0, %1, %2;" : "=r"(r.y) : "f"(v.w), "f"(v.z));
    return r;
}

static __device__ __forceinline__ void cp16(uint32_t dst, const void* src) {
    asm volatile("cp.async.cg.shared.global [%0], [%1], 16;" :: "r"(dst), "l"(src) : "memory");
}

// ---------- kernel 1: convert clsw fp32 -> fp16 scratch ----------
__global__ void cvtB_kernel(const float* __restrict__ clsw) {
    int i = blockIdx.x * blockDim.x + threadIdx.x;   // 18432 float4 chunks
    float4 v = ((const float4*)clsw)[i];
    ((uint2*)g_Bh)[i] = cvt_f16x4(v);
}

// ---------- kernel 2: gathered GEMM; A via cp.async fp32 ring ----------
__global__ __launch_bounds__(THREADS, 2)
void ner_hmma_kernel(const float* __restrict__ seq, const int* __restrict__ widx,
                     const float* __restrict__ clsb, float* __restrict__ out) {
    extern __shared__ char smem[];
    const uint32_t sb = smem_u32(smem);
    const int tid  = threadIdx.x;
    const int wid  = tid >> 5;
    const int lane = tid & 31;
    const int b  = blockIdx.x >> 2;
    const int w0 = (blockIdx.x & 3) * MT;

    int* idx_s = (int*)smem;
    if (tid < MT) idx_s[tid] = widx[b * W_DIM + w0 + tid];
    __syncthreads();

    // ---- A cp.async tasks: 64 rows x 16 chunks(16B) = 1024 -> 4/thread ----
    // Each thread later LDS-reads exactly the bytes it cp.async'd (self-visible
    // after wait_group; no barrier needed before the convert step).
    const char* aSrc[4];
    uint32_t aDst32[4];   // byte offset inside an A32 stage (linear 256 B rows)
    uint32_t aDst16[4];   // byte offset inside an A16 tile (RS=144 rows)
#pragma unroll
    for (int j = 0; j < 4; j++) {
        int u = tid + 256 * j;
        int row = u >> 4, ch = u & 15;
        aSrc[j]   = (const char*)(seq + ((size_t)b * S_DIM + idx_s[row]) * D_DIM) + ch * 16;
        aDst32[j] = (uint32_t)row * 256 + (uint32_t)ch * 16;
        aDst16[j] = (uint32_t)row * RS  + (uint32_t)ch * 8;
    }
    // ---- B cp.async tasks: 96 rows x 8 chunks(16B) = 768 -> 3/thread ----
    const unsigned char* bSrc[3];
    uint32_t bDst[3];
#pragma unroll
    for (int j = 0; j < 3; j++) {
        int u = tid + 256 * j;
        int row = u >> 3, ch = u & 7;
        bSrc[j] = g_Bh + (size_t)row * (D_DIM * 2) + ch * 16;
        bDst[j] = (uint32_t)row * RS + (uint32_t)ch * 16;
    }

    // ---- consumer mapping: 2(M) x 4(N) warp grid, warp tile 32x24 ----
    const int wm = (wid & 1) * 32;
    const int wn = (wid >> 1) * 24;
    const uint32_t aOff  = (uint32_t)(wm + (lane & 15)) * RS + ((lane >> 4) << 4);
    const uint32_t bOff4 = (uint32_t)(wn + ((lane >> 4) << 3) + (lane & 7)) * RS
                         + (((lane >> 3) & 1) << 4);
    const uint32_t bOff2 = (uint32_t)(wn + 16 + (lane & 7)) * RS
                         + (((lane >> 3) & 1) << 4);

    float acc[6][4];
#pragma unroll
    for (int i = 0; i < 6; i++)
#pragma unroll
        for (int v = 0; v < 4; v++) acc[i][v] = 0.f;

    // ---- prologue: issue async groups for tiles 0 and 1 ----
#pragma unroll
    for (int pt = 0; pt < 2; pt++) {
        const uint32_t a32 = sb + SM_A32 + pt * A32_STAGE;
        const uint32_t bS  = sb + SM_B   + pt * B_STAGE;
#pragma unroll
        for (int j = 0; j < 4; j++) cp16(a32 + aDst32[j], aSrc[j] + pt * 256);
#pragma unroll
        for (int j = 0; j < 3; j++) cp16(bS + bDst[j], bSrc[j] + pt * 128);
        asm volatile("cp.async.commit_group;" ::: "memory");
    }

    int q = 0;   // ring stage of tile t (mod 3)
    for (int t = 0; t < NUM_KT; t++) {
        // 1. tile t's group complete (allow t+1 pending)
        if (t + 1 < NUM_KT) asm volatile("cp.async.wait_group 1;" ::: "memory");
        else                asm volatile("cp.async.wait_group 0;" ::: "memory");

        // 2. convert own A chunks: LDS fp32 -> cvt -> STS fp16 (smem-only path)
        {
            const char* a32 = smem + SM_A32 + q * A32_STAGE;
            char* a16 = smem + SM_A16 + (t & 1) * A16_STAGE;
#pragma unroll
            for (int j = 0; j < 4; j++) {
                float4 v = *(const float4*)(a32 + aDst32[j]);
                *(uint2*)(a16 + aDst16[j]) = cvt_f16x4(v);
            }
        }

        // 3. publish A16(t) stores + B(t) cp.async to all warps
        __syncthreads();

        // 4. issue group for tile t+2 into stage (t+2)%3 (2-tile cover)
        if (t + 2 < NUM_KT) {
            const int tn = t + 2;
            const int qn = (q + 2 >= 3) ? q - 1 : q + 2;
            const uint32_t a32 = sb + SM_A32 + qn * A32_STAGE;
            const uint32_t bS  = sb + SM_B   + qn * B_STAGE;
#pragma unroll
            for (int j = 0; j < 4; j++) cp16(a32 + aDst32[j], aSrc[j] + tn * 256);
#pragma unroll
            for (int j = 0; j < 3; j++) cp16(bS + bDst[j], bSrc[j] + tn * 128);
            asm volatile("cp.async.commit_group;" ::: "memory");
        }

        // 5. compute(t)
        const uint32_t sA = sb + SM_A16 + (t & 1) * A16_STAGE;
        const uint32_t sB = sb + SM_B + q * B_STAGE;
#pragma unroll
        for (int ks = 0; ks < 4; ks++) {
            const uint32_t k0b = (uint32_t)ks * 32;   // 16 fp16 = 32 B
            uint32_t af[2][4];
#pragma unroll
            for (int i = 0; i < 2; i++)
                ldsm4(af[i], sA + aOff + i * (16 * RS) + k0b);
            uint32_t bf[6];
            ldsm4(bf,     sB + bOff4 + k0b);
            ldsm2(bf + 4, sB + bOff2 + k0b);
#pragma unroll
            for (int i = 0; i < 2; i++)
#pragma unroll
                for (int j = 0; j < 3; j++)
                    mma_f16(acc[i * 3 + j], af[i], &bf[j * 2]);
        }

        q = (q + 1 >= 3) ? 0 : q + 1;
    }

    // ---- epilogue: scatter to out[a, b, w, c] ----
#pragma unroll
    for (int i = 0; i < 2; i++) {
#pragma unroll
        for (int j = 0; j < 3; j++) {
            const float* c = acc[i * 3 + j];
            const int n_base = wn + j * 8 + 2 * (lane & 3);
            const int m_base = wm + i * 16 + (lane >> 2);
#pragma unroll
            for (int v = 0; v < 4; v++) {
                const int n = n_base + (v & 1);
                const int m = m_base + (v >> 1) * 8;
                const int w = w0 + m;
                const int a_ = n / 3;
                const int c_ = n - a_ * 3;
                out[(size_t)a_ * (B_DIM * W_DIM * 3) + (size_t)b * (W_DIM * 3) + w * 3 + c_]
                    = c[v] + clsb[n];
            }
        }
    }
}

extern "C" void kernel_launch(void* const* d_in, const int* in_sizes, int n_in,
                              void* d_out, int out_size) {
    const float* seq  = (const float*)d_in[0];  // [B, S, D] fp32
    const int*   widx = (const int*)d_in[1];    // [B, W] int32
    const float* clsw = (const float*)d_in[2];  // [A*3, D] fp32
    const float* clsb = (const float*)d_in[3];  // [A*3] fp32
    float* out = (float*)d_out;                 // [A, B, W, 3] fp32

    cvtB_kernel<<<36, 512>>>(clsw);
    cudaFuncSetAttribute(ner_hmma_kernel, cudaFuncAttributeMaxDynamicSharedMemorySize, SMEM_TOTAL);
    ner_hmma_kernel<<<256, THREADS, SMEM_TOTAL>>>(seq, widx, clsb, out);
}